// round 14
// baseline (speedup 1.0000x reference)
#include <cuda_runtime.h>
#include <cuda_fp16.h>
#include <cstdint>

// ---------------------------------------------------------------------------
// KAN forward, 2 layers, B=8192, d=1024. Fused GEMM h = Aaug @ Wpack^T.
// Precision (measured-calibrated): single fp16 product, fp32 accumulation;
// rel_err 4.5e-4 (2.2x under the 1e-3 gate, deterministic bench).
// R14: exploit cubic B-spline 4-wide support -- compute the four standard
// cubic polynomials of t=frac(u0) once, place into the 8 basis slots with
// integer-compare selects (rebalances fma-pipe work onto the alu pipe).
// Identical values to the R13 closed form (incl. t=0 continuity, exact
// zeros outside support).
// ---------------------------------------------------------------------------

#define BATCH 8192
#define DIN   1024
#define DOUT  1024
#define KHALF 9216           // 1024 gelu + 8192 bases
#define NKNOTS 12

#define TILE_M 128
#define TILE_N 128
#define BK     64
#define STAGES 3
#define ROWB   144           // 128 data bytes + 16 pad per smem row
#define A_BYTES (TILE_M * ROWB)            // 18432
#define B_BYTES (TILE_N * ROWB)            // 18432
#define STAGE_BYTES (A_BYTES + B_BYTES)    // 36864
#define SMEM_TOTAL (STAGES * STAGE_BYTES)  // 110592 -> 2 CTAs/SM

#define TILES   512                         // (8192/128) x (1024/128)
#define NTASKS  (4 * TILES)                 // 2048

__device__ __align__(128) __half g_A[(size_t)BATCH * KHALF];      // 151 MiB
__device__ __align__(128) __half g_W[2 * (size_t)DOUT * KHALF];   // 37.7 MiB
__device__ float  g_hp[4 * (size_t)BATCH * DOUT];                 // 128 MiB

// ------------------------------- helpers -----------------------------------
__device__ __forceinline__ uint32_t smem_u32(const void* p) {
    uint32_t a;
    asm("{ .reg .u64 t; cvta.to.shared.u64 t, %1; cvt.u32.u64 %0, t; }" : "=r"(a) : "l"(p));
    return a;
}
__device__ __forceinline__ void cp_async16(uint32_t s, const void* g) {
    asm volatile("cp.async.cg.shared.global [%0], [%1], 16;" :: "r"(s), "l"(g));
}
#define CP_COMMIT() asm volatile("cp.async.commit_group;" ::: "memory")
#define CP_WAIT1()  asm volatile("cp.async.wait_group 1;" ::: "memory")

__device__ __forceinline__ void ldsm_x4(uint32_t& r0, uint32_t& r1, uint32_t& r2,
                                        uint32_t& r3, uint32_t addr) {
    asm volatile("ldmatrix.sync.aligned.m8n8.x4.shared.b16 {%0,%1,%2,%3}, [%4];"
                 : "=r"(r0), "=r"(r1), "=r"(r2), "=r"(r3) : "r"(addr));
}
__device__ __forceinline__ void mma16816_f32(float* d, const uint32_t* a,
                                             uint32_t b0, uint32_t b1) {
    asm volatile("mma.sync.aligned.m16n8k16.row.col.f32.f16.f16.f32 "
                 "{%0,%1,%2,%3}, {%4,%5,%6,%7}, {%8,%9}, {%0,%1,%2,%3};"
                 : "+f"(d[0]), "+f"(d[1]), "+f"(d[2]), "+f"(d[3])
                 : "r"(a[0]), "r"(a[1]), "r"(a[2]), "r"(a[3]), "r"(b0), "r"(b1));
}

// Expansion: gelu + 8 cardinal-cubic B-spline bases.
// u0 = (xv - g0)/h. Only bases c in {i0-3..i0} (i0=floor(u0)) are nonzero;
// their values are the 4 standard cubic polys of t = u0 - i0:
//   c=i0:   t^3/6
//   c=i0-1: (4 - 6(1-t)^2 + 3(1-t)^3)/6
//   c=i0-2: (4 - 6t^2 + 3t^3)/6
//   c=i0-3: (1-t)^3/6
__device__ __forceinline__ void expand_one(float xv, float u0,
                                           __half* Arow, int i)
{
    float fi = floorf(u0);
    int   i0 = (int)fi;
    float t  = u0 - fi;
    float s  = 1.0f - t;
    float t2 = t * t, s2 = s * s;
    const float r6 = 1.0f / 6.0f;
    float q3 = t * t2 * r6;                               // t^3/6
    float q0 = s * s2 * r6;                               // (1-t)^3/6
    float q2 = fmaf(s2, fmaf(3.0f, s, -6.0f), 4.0f) * r6; // (4-6s^2+3s^3)/6
    float q1 = fmaf(t2, fmaf(3.0f, t, -6.0f), 4.0f) * r6; // (4-6t^2+3t^3)/6

    __half hi[8];
#pragma unroll
    for (int c = 0; c < 8; c++) {
        int dc = i0 - c;
        float B = (dc == 0) ? q3 : (dc == 1) ? q2 : (dc == 2) ? q1
                : (dc == 3) ? q0 : 0.0f;
        hi[c] = __float2half_rn(B);
    }
    Arow[i] = __float2half_rn(xv * normcdff(xv));
    *(uint4*)(Arow + DIN + 8 * i) = *(uint4*)hi;
}

// ---------------------------------------------------------------------------
// Layer-0 expansion: external x -> g_A. Grid is a broadcast row.
// ---------------------------------------------------------------------------
__global__ void expand_kernel(const float* __restrict__ xin,
                              const float* __restrict__ grid)
{
    int e = blockIdx.x * blockDim.x + threadIdx.x;
    int i = e & (DIN - 1);
    float g0 = __ldg(grid);
    float rh = 1.0f / (__ldg(grid + 1) - g0);
    float xv = xin[e];
    expand_one(xv, (xv - g0) * rh, g_A + (size_t)(e >> 10) * KHALF, i);
}

// ---------------------------------------------------------------------------
// Weight packing (fp16), both layers at once.
// ---------------------------------------------------------------------------
__global__ void pack_w_kernel(const float* __restrict__ bw,
                              const float* __restrict__ sw)
{
    int e = blockIdx.x * blockDim.x + threadIdx.x;  // layer*1M + o*1024 + i
    int i = e & (DIN - 1);
    __half* W = g_W + (size_t)(e >> 10) * KHALF;    // (layer*DOUT + o) rows

    W[i] = __float2half_rn(bw[e]);

    const float* s = sw + (size_t)e * 8;
    __half hi[8];
#pragma unroll
    for (int c = 0; c < 8; c++) hi[c] = __float2half_rn(s[c]);
    *(uint4*)(W + DIN + 8 * i) = *(uint4*)hi;
}

// ---------------------------------------------------------------------------
// GEMM. blockIdx.x in [0,2048): K-quarter phase x 128x128 tile.
//   phase p: A x B over K [p*2304, (p+1)*2304), fp32 acc -> g_hp[p]
// 8 warps (2x4), warp tile 64x32. 3-stage cp.async, 2 CTAs/SM.
// ---------------------------------------------------------------------------
__global__ void __launch_bounds__(256, 2) gemm_kernel(int layer)
{
    extern __shared__ __align__(128) char smem[];
    const uint32_t sb = smem_u32(smem);

    const int task  = blockIdx.x;
    const int phase = task >> 9;               // 0..3
    const int r     = task & 511;
    const int bm    = (r & 63) * TILE_M;
    const int bn    = (r >> 6) * TILE_N;

    const int tid = threadIdx.x;
    const int l   = tid & 31;
    const int wid = tid >> 5;
    const int wm  = wid >> 2;                  // 0..1
    const int wn  = wid & 3;                   // 0..3

    const int KIT = 36;
    const size_t k0 = (size_t)phase * 36 * BK;

    const int ld_row = tid >> 3;
    const int ld_kc  = tid & 7;
    const __half* gA = g_A + (size_t)(bm + ld_row) * KHALF + ld_kc * 8 + k0;
    const __half* gB = g_W + ((size_t)layer * DOUT + bn + ld_row) * KHALF + ld_kc * 8 + k0;
    const uint32_t sA  = sb + ld_row * ROWB + ld_kc * 16;
    const uint32_t sBs = sb + A_BYTES + ld_row * ROWB + ld_kc * 16;

    const uint32_t a_lrow = (uint32_t)(l & 15);
    const uint32_t a_lkb  = (uint32_t)((l >> 4) * 16);
    const uint32_t b_lrow = (uint32_t)((l & 7) + ((l & 16) >> 1));
    const uint32_t b_lkb  = (uint32_t)((l & 8) * 2);

    auto issue = [&](int it, int stage) {
        size_t k = (size_t)it * BK;
        uint32_t so = (uint32_t)(stage * STAGE_BYTES);
        const __half* ga = gA + k;
        const __half* gb = gB + k;
#pragma unroll
        for (int q = 0; q < 4; q++)
            cp_async16(sA + so + q * 32 * ROWB, ga + (size_t)q * 32 * KHALF);
#pragma unroll
        for (int q = 0; q < 4; q++)
            cp_async16(sBs + so + q * 32 * ROWB, gb + (size_t)q * 32 * KHALF);
    };

    float acc[4][4][4];
#pragma unroll
    for (int i = 0; i < 4; i++)
#pragma unroll
        for (int j = 0; j < 4; j++)
#pragma unroll
            for (int q = 0; q < 4; q++) acc[i][j][q] = 0.0f;

    issue(0, 0); CP_COMMIT();
    issue(1, 1); CP_COMMIT();

    for (int it = 0; it < KIT; it++) {
        int cur = it % STAGES;
        CP_WAIT1();
        __syncthreads();
        if (it + 2 < KIT) issue(it + 2, (it + 2) % STAGES);
        CP_COMMIT();

        const uint32_t As = sb + cur * STAGE_BYTES;
        const uint32_t Bs = As + A_BYTES;

#pragma unroll
        for (int kk = 0; kk < 4; kk++) {
            uint32_t a[4][4], b[2][4];
#pragma unroll
            for (int i = 0; i < 4; i++)
                ldsm_x4(a[i][0], a[i][1], a[i][2], a[i][3],
                        As + (wm * 64 + i * 16 + a_lrow) * ROWB + kk * 32 + a_lkb);
#pragma unroll
            for (int j2 = 0; j2 < 2; j2++)
                ldsm_x4(b[j2][0], b[j2][1], b[j2][2], b[j2][3],
                        Bs + (wn * 32 + j2 * 16 + b_lrow) * ROWB + kk * 32 + b_lkb);
#pragma unroll
            for (int i = 0; i < 4; i++)
#pragma unroll
                for (int j = 0; j < 4; j++)
                    mma16816_f32(acc[i][j], a[i], b[j >> 1][(j & 1) * 2],
                                 b[j >> 1][(j & 1) * 2 + 1]);
        }
    }

    const int g = l >> 2;
    const int t = l & 3;
    const int row0 = bm + wm * 64 + g;
    const int col0 = bn + wn * 32 + t * 2;
    float* hout = g_hp + (size_t)phase * BATCH * DOUT;
#pragma unroll
    for (int i = 0; i < 4; i++)
#pragma unroll
        for (int j = 0; j < 4; j++) {
            float* p0 = hout + (size_t)(row0 + i * 16) * DOUT + col0 + j * 8;
            *(float2*)p0              = make_float2(acc[i][j][0], acc[i][j][1]);
            *(float2*)(p0 + 8 * DOUT) = make_float2(acc[i][j][2], acc[i][j][3]);
        }
}

// ---------------------------------------------------------------------------
// Shared LN core: sum 4 partials, LayerNorm, PReLU -> 4 activations.
// ---------------------------------------------------------------------------
__device__ __forceinline__ float4 ln_core(const float* gam, const float* bet,
                                          const float* pa, int row, int tid)
{
    size_t off = (size_t)row * DOUT + tid * 4;
    const size_t HSZ = (size_t)BATCH * DOUT;

    float4 v = *(const float4*)(g_hp + off);
#pragma unroll
    for (int p = 1; p < 4; p++) {
        float4 u = *(const float4*)(g_hp + p * HSZ + off);
        v.x += u.x; v.y += u.y; v.z += u.z; v.w += u.w;
    }

    float s  = v.x + v.y + v.z + v.w;
    float ss = v.x * v.x + v.y * v.y + v.z * v.z + v.w * v.w;
#pragma unroll
    for (int o = 16; o; o >>= 1) {
        s  += __shfl_down_sync(0xffffffffu, s, o);
        ss += __shfl_down_sync(0xffffffffu, ss, o);
    }
    __shared__ float sm[8], sm2[8];
    if ((tid & 31) == 0) { sm[tid >> 5] = s; sm2[tid >> 5] = ss; }
    __syncthreads();
    float tot = 0.0f, tot2 = 0.0f;
#pragma unroll
    for (int j = 0; j < 8; j++) { tot += sm[j]; tot2 += sm2[j]; }

    const float inv = 1.0f / (float)DOUT;
    float mu   = tot * inv;
    float var  = tot2 * inv - mu * mu;
    float rstd = rsqrtf(var + 1e-5f);
    float a    = __ldg(pa);

    float4 gm = *(const float4*)(gam + tid * 4);
    float4 bt = *(const float4*)(bet + tid * 4);

    float4 o4;
    o4.x = (v.x - mu) * rstd * gm.x + bt.x;
    o4.y = (v.y - mu) * rstd * gm.y + bt.y;
    o4.z = (v.z - mu) * rstd * gm.z + bt.z;
    o4.w = (v.w - mu) * rstd * gm.w + bt.w;
    o4.x = o4.x >= 0.0f ? o4.x : a * o4.x;
    o4.y = o4.y >= 0.0f ? o4.y : a * o4.y;
    o4.z = o4.z >= 0.0f ? o4.z : a * o4.z;
    o4.w = o4.w >= 0.0f ? o4.w : a * o4.w;
    return o4;
}

// Boundary: LN + PReLU + expansion for the next layer, fused. Writes g_A.
__global__ void ln_expand_kernel(const float* __restrict__ gam,
                                 const float* __restrict__ bet,
                                 const float* __restrict__ pa,
                                 const float* __restrict__ grid)
{
    int row = blockIdx.x;
    int tid = threadIdx.x;
    float4 o4 = ln_core(gam, bet, pa, row, tid);

    float g0 = __ldg(grid);
    float rh = 1.0f / (__ldg(grid + 1) - g0);

    __half* Arow = g_A + (size_t)row * KHALF;
    int i0 = tid * 4;
    expand_one(o4.x, (o4.x - g0) * rh, Arow, i0);
    expand_one(o4.y, (o4.y - g0) * rh, Arow, i0 + 1);
    expand_one(o4.z, (o4.z - g0) * rh, Arow, i0 + 2);
    expand_one(o4.w, (o4.w - g0) * rh, Arow, i0 + 3);
}

// Final: LN + PReLU -> output.
__global__ void ln_out_kernel(const float* __restrict__ gam,
                              const float* __restrict__ bet,
                              const float* __restrict__ pa,
                              float* __restrict__ out)
{
    int row = blockIdx.x;
    int tid = threadIdx.x;
    float4 o4 = ln_core(gam, bet, pa, row, tid);
    *(float4*)(out + (size_t)row * DOUT + tid * 4) = o4;
}

// ---------------------------------------------------------------------------
// Launch
// ---------------------------------------------------------------------------
extern "C" void kernel_launch(void* const* d_in, const int* in_sizes, int n_in,
                              void* d_out, int out_size)
{
    const float* x    = (const float*)d_in[0];
    const float* bw   = (const float*)d_in[1];
    const float* sw   = (const float*)d_in[2];
    const float* lng  = (const float*)d_in[3];
    const float* lnb  = (const float*)d_in[4];
    const float* pa   = (const float*)d_in[5];
    const float* grid = (const float*)d_in[6];
    float* out = (float*)d_out;

    cudaFuncSetAttribute(gemm_kernel, cudaFuncAttributeMaxDynamicSharedMemorySize,
                         SMEM_TOTAL);

    const int nexp  = (BATCH * DIN) / 256;
    const int npack = (2 * DOUT * DIN) / 256;   // both layers

    pack_w_kernel<<<npack, 256>>>(bw, sw);
    expand_kernel<<<nexp, 256>>>(x, grid);                       // layer-0 A
    gemm_kernel<<<NTASKS, 256, SMEM_TOTAL>>>(0);
    ln_expand_kernel<<<BATCH, 256>>>(lng, lnb, pa,
                                     grid + DIN * NKNOTS);       // boundary
    gemm_kernel<<<NTASKS, 256, SMEM_TOTAL>>>(1);
    ln_out_kernel<<<BATCH, 256>>>(lng + DOUT, lnb + DOUT, pa + 1, out);
}

// round 15
// speedup vs baseline: 1.0647x; 1.0647x over previous
#include <cuda_runtime.h>
#include <cuda_fp16.h>
#include <cstdint>

// ---------------------------------------------------------------------------
// KAN forward, 2 layers, B=8192, d=1024. Fused GEMM h = Aaug @ Wpack^T.
// Precision (measured-calibrated): single fp16 product, fp32 accumulation;
// rel_err 4.5e-4 (2.2x under the 1e-3 gate, deterministic bench).
// R15 = R13 (closed-form cardinal-cubic bases, piecewise kernel eval;
// R14's select-placement variant issued MORE instructions and regressed)
// + coalesced 8-byte gelu store in ln_expand (was 4x 2-byte stores/thread).
// ---------------------------------------------------------------------------

#define BATCH 8192
#define DIN   1024
#define DOUT  1024
#define KHALF 9216           // 1024 gelu + 8192 bases
#define NKNOTS 12

#define TILE_M 128
#define TILE_N 128
#define BK     64
#define STAGES 3
#define ROWB   144           // 128 data bytes + 16 pad per smem row
#define A_BYTES (TILE_M * ROWB)            // 18432
#define B_BYTES (TILE_N * ROWB)            // 18432
#define STAGE_BYTES (A_BYTES + B_BYTES)    // 36864
#define SMEM_TOTAL (STAGES * STAGE_BYTES)  // 110592 -> 2 CTAs/SM

#define TILES   512                         // (8192/128) x (1024/128)
#define NTASKS  (4 * TILES)                 // 2048

__device__ __align__(128) __half g_A[(size_t)BATCH * KHALF];      // 151 MiB
__device__ __align__(128) __half g_W[2 * (size_t)DOUT * KHALF];   // 37.7 MiB
__device__ float  g_hp[4 * (size_t)BATCH * DOUT];                 // 128 MiB

// ------------------------------- helpers -----------------------------------
__device__ __forceinline__ uint32_t smem_u32(const void* p) {
    uint32_t a;
    asm("{ .reg .u64 t; cvta.to.shared.u64 t, %1; cvt.u32.u64 %0, t; }" : "=r"(a) : "l"(p));
    return a;
}
__device__ __forceinline__ void cp_async16(uint32_t s, const void* g) {
    asm volatile("cp.async.cg.shared.global [%0], [%1], 16;" :: "r"(s), "l"(g));
}
#define CP_COMMIT() asm volatile("cp.async.commit_group;" ::: "memory")
#define CP_WAIT1()  asm volatile("cp.async.wait_group 1;" ::: "memory")

__device__ __forceinline__ void ldsm_x4(uint32_t& r0, uint32_t& r1, uint32_t& r2,
                                        uint32_t& r3, uint32_t addr) {
    asm volatile("ldmatrix.sync.aligned.m8n8.x4.shared.b16 {%0,%1,%2,%3}, [%4];"
                 : "=r"(r0), "=r"(r1), "=r"(r2), "=r"(r3) : "r"(addr));
}
__device__ __forceinline__ void mma16816_f32(float* d, const uint32_t* a,
                                             uint32_t b0, uint32_t b1) {
    asm volatile("mma.sync.aligned.m16n8k16.row.col.f32.f16.f16.f32 "
                 "{%0,%1,%2,%3}, {%4,%5,%6,%7}, {%8,%9}, {%0,%1,%2,%3};"
                 : "+f"(d[0]), "+f"(d[1]), "+f"(d[2]), "+f"(d[3])
                 : "r"(a[0]), "r"(a[1]), "r"(a[2]), "r"(a[3]), "r"(b0), "r"(b1));
}

// Closed-form cardinal cubic B-spline bases (R13 form).
// u0 = (xv - g0)/h. Basis c: v = u0 - c, d = min(|v-2|,2),
//   B = (d<=1) ? (4 - 6d^2 + 3d^3)/6 : (2-d)^3/6.
// Writes only the 8 bases (16B); gelu half is returned for batched storing.
__device__ __forceinline__ __half expand_bases(float xv, float u0,
                                               __half* Arow, int i)
{
    __half hi[8];
#pragma unroll
    for (int c = 0; c < 8; c++) {
        float v  = u0 - (float)c;
        float d  = fminf(fabsf(v - 2.0f), 2.0f);
        float d2 = d * d;
        float p1 = fmaf(d2, fmaf(3.0f, d, -6.0f), 4.0f);  // 4 - 6d^2 + 3d^3
        float s  = 2.0f - d;
        float p2 = s * s * s;
        float B  = (d <= 1.0f) ? p1 : p2;
        hi[c] = __float2half_rn(B * (1.0f / 6.0f));
    }
    *(uint4*)(Arow + DIN + 8 * i) = *(uint4*)hi;
    return __float2half_rn(xv * normcdff(xv));
}

// ---------------------------------------------------------------------------
// Layer-0 expansion: external x -> g_A. Grid is a broadcast row.
// ---------------------------------------------------------------------------
__global__ void expand_kernel(const float* __restrict__ xin,
                              const float* __restrict__ grid)
{
    int e = blockIdx.x * blockDim.x + threadIdx.x;
    int i = e & (DIN - 1);
    float g0 = __ldg(grid);
    float rh = 1.0f / (__ldg(grid + 1) - g0);
    float xv = xin[e];
    __half* Arow = g_A + (size_t)(e >> 10) * KHALF;
    Arow[i] = expand_bases(xv, (xv - g0) * rh, Arow, i);
}

// ---------------------------------------------------------------------------
// Weight packing (fp16), both layers at once.
// ---------------------------------------------------------------------------
__global__ void pack_w_kernel(const float* __restrict__ bw,
                              const float* __restrict__ sw)
{
    int e = blockIdx.x * blockDim.x + threadIdx.x;  // layer*1M + o*1024 + i
    int i = e & (DIN - 1);
    __half* W = g_W + (size_t)(e >> 10) * KHALF;    // (layer*DOUT + o) rows

    W[i] = __float2half_rn(bw[e]);

    const float* s = sw + (size_t)e * 8;
    __half hi[8];
#pragma unroll
    for (int c = 0; c < 8; c++) hi[c] = __float2half_rn(s[c]);
    *(uint4*)(W + DIN + 8 * i) = *(uint4*)hi;
}

// ---------------------------------------------------------------------------
// GEMM. blockIdx.x in [0,2048): K-quarter phase x 128x128 tile.
//   phase p: A x B over K [p*2304, (p+1)*2304), fp32 acc -> g_hp[p]
// 8 warps (2x4), warp tile 64x32. 3-stage cp.async, 2 CTAs/SM.
// ---------------------------------------------------------------------------
__global__ void __launch_bounds__(256, 2) gemm_kernel(int layer)
{
    extern __shared__ __align__(128) char smem[];
    const uint32_t sb = smem_u32(smem);

    const int task  = blockIdx.x;
    const int phase = task >> 9;               // 0..3
    const int r     = task & 511;
    const int bm    = (r & 63) * TILE_M;
    const int bn    = (r >> 6) * TILE_N;

    const int tid = threadIdx.x;
    const int l   = tid & 31;
    const int wid = tid >> 5;
    const int wm  = wid >> 2;                  // 0..1
    const int wn  = wid & 3;                   // 0..3

    const int KIT = 36;
    const size_t k0 = (size_t)phase * 36 * BK;

    const int ld_row = tid >> 3;
    const int ld_kc  = tid & 7;
    const __half* gA = g_A + (size_t)(bm + ld_row) * KHALF + ld_kc * 8 + k0;
    const __half* gB = g_W + ((size_t)layer * DOUT + bn + ld_row) * KHALF + ld_kc * 8 + k0;
    const uint32_t sA  = sb + ld_row * ROWB + ld_kc * 16;
    const uint32_t sBs = sb + A_BYTES + ld_row * ROWB + ld_kc * 16;

    const uint32_t a_lrow = (uint32_t)(l & 15);
    const uint32_t a_lkb  = (uint32_t)((l >> 4) * 16);
    const uint32_t b_lrow = (uint32_t)((l & 7) + ((l & 16) >> 1));
    const uint32_t b_lkb  = (uint32_t)((l & 8) * 2);

    auto issue = [&](int it, int stage) {
        size_t k = (size_t)it * BK;
        uint32_t so = (uint32_t)(stage * STAGE_BYTES);
        const __half* ga = gA + k;
        const __half* gb = gB + k;
#pragma unroll
        for (int q = 0; q < 4; q++)
            cp_async16(sA + so + q * 32 * ROWB, ga + (size_t)q * 32 * KHALF);
#pragma unroll
        for (int q = 0; q < 4; q++)
            cp_async16(sBs + so + q * 32 * ROWB, gb + (size_t)q * 32 * KHALF);
    };

    float acc[4][4][4];
#pragma unroll
    for (int i = 0; i < 4; i++)
#pragma unroll
        for (int j = 0; j < 4; j++)
#pragma unroll
            for (int q = 0; q < 4; q++) acc[i][j][q] = 0.0f;

    issue(0, 0); CP_COMMIT();
    issue(1, 1); CP_COMMIT();

    for (int it = 0; it < KIT; it++) {
        int cur = it % STAGES;
        CP_WAIT1();
        __syncthreads();
        if (it + 2 < KIT) issue(it + 2, (it + 2) % STAGES);
        CP_COMMIT();

        const uint32_t As = sb + cur * STAGE_BYTES;
        const uint32_t Bs = As + A_BYTES;

#pragma unroll
        for (int kk = 0; kk < 4; kk++) {
            uint32_t a[4][4], b[2][4];
#pragma unroll
            for (int i = 0; i < 4; i++)
                ldsm_x4(a[i][0], a[i][1], a[i][2], a[i][3],
                        As + (wm * 64 + i * 16 + a_lrow) * ROWB + kk * 32 + a_lkb);
#pragma unroll
            for (int j2 = 0; j2 < 2; j2++)
                ldsm_x4(b[j2][0], b[j2][1], b[j2][2], b[j2][3],
                        Bs + (wn * 32 + j2 * 16 + b_lrow) * ROWB + kk * 32 + b_lkb);
#pragma unroll
            for (int i = 0; i < 4; i++)
#pragma unroll
                for (int j = 0; j < 4; j++)
                    mma16816_f32(acc[i][j], a[i], b[j >> 1][(j & 1) * 2],
                                 b[j >> 1][(j & 1) * 2 + 1]);
        }
    }

    const int g = l >> 2;
    const int t = l & 3;
    const int row0 = bm + wm * 64 + g;
    const int col0 = bn + wn * 32 + t * 2;
    float* hout = g_hp + (size_t)phase * BATCH * DOUT;
#pragma unroll
    for (int i = 0; i < 4; i++)
#pragma unroll
        for (int j = 0; j < 4; j++) {
            float* p0 = hout + (size_t)(row0 + i * 16) * DOUT + col0 + j * 8;
            *(float2*)p0              = make_float2(acc[i][j][0], acc[i][j][1]);
            *(float2*)(p0 + 8 * DOUT) = make_float2(acc[i][j][2], acc[i][j][3]);
        }
}

// ---------------------------------------------------------------------------
// Shared LN core: sum 4 partials, LayerNorm, PReLU -> 4 activations.
// ---------------------------------------------------------------------------
__device__ __forceinline__ float4 ln_core(const float* gam, const float* bet,
                                          const float* pa, int row, int tid)
{
    size_t off = (size_t)row * DOUT + tid * 4;
    const size_t HSZ = (size_t)BATCH * DOUT;

    float4 v = *(const float4*)(g_hp + off);
#pragma unroll
    for (int p = 1; p < 4; p++) {
        float4 u = *(const float4*)(g_hp + p * HSZ + off);
        v.x += u.x; v.y += u.y; v.z += u.z; v.w += u.w;
    }

    float s  = v.x + v.y + v.z + v.w;
    float ss = v.x * v.x + v.y * v.y + v.z * v.z + v.w * v.w;
#pragma unroll
    for (int o = 16; o; o >>= 1) {
        s  += __shfl_down_sync(0xffffffffu, s, o);
        ss += __shfl_down_sync(0xffffffffu, ss, o);
    }
    __shared__ float sm[8], sm2[8];
    if ((tid & 31) == 0) { sm[tid >> 5] = s; sm2[tid >> 5] = ss; }
    __syncthreads();
    float tot = 0.0f, tot2 = 0.0f;
#pragma unroll
    for (int j = 0; j < 8; j++) { tot += sm[j]; tot2 += sm2[j]; }

    const float inv = 1.0f / (float)DOUT;
    float mu   = tot * inv;
    float var  = tot2 * inv - mu * mu;
    float rstd = rsqrtf(var + 1e-5f);
    float a    = __ldg(pa);

    float4 gm = *(const float4*)(gam + tid * 4);
    float4 bt = *(const float4*)(bet + tid * 4);

    float4 o4;
    o4.x = (v.x - mu) * rstd * gm.x + bt.x;
    o4.y = (v.y - mu) * rstd * gm.y + bt.y;
    o4.z = (v.z - mu) * rstd * gm.z + bt.z;
    o4.w = (v.w - mu) * rstd * gm.w + bt.w;
    o4.x = o4.x >= 0.0f ? o4.x : a * o4.x;
    o4.y = o4.y >= 0.0f ? o4.y : a * o4.y;
    o4.z = o4.z >= 0.0f ? o4.z : a * o4.z;
    o4.w = o4.w >= 0.0f ? o4.w : a * o4.w;
    return o4;
}

// Boundary: LN + PReLU + expansion for the next layer, fused. Writes g_A.
__global__ void ln_expand_kernel(const float* __restrict__ gam,
                                 const float* __restrict__ bet,
                                 const float* __restrict__ pa,
                                 const float* __restrict__ grid)
{
    int row = blockIdx.x;
    int tid = threadIdx.x;
    float4 o4 = ln_core(gam, bet, pa, row, tid);

    float g0 = __ldg(grid);
    float rh = 1.0f / (__ldg(grid + 1) - g0);

    __half* Arow = g_A + (size_t)row * KHALF;
    int i0 = tid * 4;
    // Bases written per element; gelu halves batched into one 8-byte store.
    __half ge[4];
    ge[0] = expand_bases(o4.x, (o4.x - g0) * rh, Arow, i0);
    ge[1] = expand_bases(o4.y, (o4.y - g0) * rh, Arow, i0 + 1);
    ge[2] = expand_bases(o4.z, (o4.z - g0) * rh, Arow, i0 + 2);
    ge[3] = expand_bases(o4.w, (o4.w - g0) * rh, Arow, i0 + 3);
    *(uint2*)(Arow + i0) = *(uint2*)ge;
}

// Final: LN + PReLU -> output.
__global__ void ln_out_kernel(const float* __restrict__ gam,
                              const float* __restrict__ bet,
                              const float* __restrict__ pa,
                              float* __restrict__ out)
{
    int row = blockIdx.x;
    int tid = threadIdx.x;
    float4 o4 = ln_core(gam, bet, pa, row, tid);
    *(float4*)(out + (size_t)row * DOUT + tid * 4) = o4;
}

// ---------------------------------------------------------------------------
// Launch
// ---------------------------------------------------------------------------
extern "C" void kernel_launch(void* const* d_in, const int* in_sizes, int n_in,
                              void* d_out, int out_size)
{
    const float* x    = (const float*)d_in[0];
    const float* bw   = (const float*)d_in[1];
    const float* sw   = (const float*)d_in[2];
    const float* lng  = (const float*)d_in[3];
    const float* lnb  = (const float*)d_in[4];
    const float* pa   = (const float*)d_in[5];
    const float* grid = (const float*)d_in[6];
    float* out = (float*)d_out;

    cudaFuncSetAttribute(gemm_kernel, cudaFuncAttributeMaxDynamicSharedMemorySize,
                         SMEM_TOTAL);

    const int nexp  = (BATCH * DIN) / 256;
    const int npack = (2 * DOUT * DIN) / 256;   // both layers

    pack_w_kernel<<<npack, 256>>>(bw, sw);
    expand_kernel<<<nexp, 256>>>(x, grid);                       // layer-0 A
    gemm_kernel<<<NTASKS, 256, SMEM_TOTAL>>>(0);
    ln_expand_kernel<<<BATCH, 256>>>(lng, lnb, pa,
                                     grid + DIN * NKNOTS);       // boundary
    gemm_kernel<<<NTASKS, 256, SMEM_TOTAL>>>(1);
    ln_out_kernel<<<BATCH, 256>>>(lng + DOUT, lnb + DOUT, pa + 1, out);
}